// round 4
// baseline (speedup 1.0000x reference)
#include <cuda_runtime.h>
#include <cuda_bf16.h>
#include <mma.h>
#include <math_constants.h>

using namespace nvcuda;

// Problem dims
#define Bb   64
#define Ll   25
#define Ff   128
#define Pp   10000
#define Rr   (Bb*Ll)        // 1600 rows
#define MP   10112          // P padded to 79*128 for GEMM tiles

// ---------------- device scratch ----------------
// stats layout (int bits of nonnegative floats):
// 0 ds_max, 1 ds_min, 2 dt_max, 3 dt_min, 4 is_max, 5 is_min, 6 ti_max, 7 ti_min
__device__ int   g_stats[8];
__device__ float g_ti[Rr];
__device__ float g_sao[Rr * Ff];
__device__ float g_embT[Ff * MP];          // 5.2 MB  (poi_emb transposed, zero-padded cols)
__device__ float g_M[Rr * MP];             // 64.7 MB (sao @ poi_emb^T)

// ---------------- helpers ----------------
__device__ __forceinline__ float hav(float lat1, float lon1, float lat2, float lon2) {
    const float pc = 0.017453292519943295f;  // pi/180
    float a = 0.5f - cosf((lat2 - lat1) * pc) * 0.5f
            + cosf(lat1 * pc) * cosf(lat2 * pc) * (1.0f - cosf((lon2 - lon1) * pc)) * 0.5f;
    a = fminf(fmaxf(a, 0.0f), 1.0f);
    return 12742.0f * asinf(sqrtf(a));
}

// block min/max reduce + atomic into g_stats (values are nonnegative -> int-bit ordering OK)
__device__ __forceinline__ void blockMinMaxAtomic(float vmax, float vmin, int idxMax, int idxMin) {
    #pragma unroll
    for (int off = 16; off; off >>= 1) {
        vmax = fmaxf(vmax, __shfl_xor_sync(0xffffffffu, vmax, off));
        vmin = fminf(vmin, __shfl_xor_sync(0xffffffffu, vmin, off));
    }
    __shared__ float smax[8], smin[8];
    int warp = threadIdx.x >> 5, lane = threadIdx.x & 31;
    int nw = (blockDim.x + 31) >> 5;
    if (lane == 0) { smax[warp] = vmax; smin[warp] = vmin; }
    __syncthreads();
    if (warp == 0) {
        vmax = (lane < nw) ? smax[lane] : -CUDART_INF_F;
        vmin = (lane < nw) ? smin[lane] :  CUDART_INF_F;
        #pragma unroll
        for (int off = 4; off; off >>= 1) {
            vmax = fmaxf(vmax, __shfl_xor_sync(0xffffffffu, vmax, off));
            vmin = fminf(vmin, __shfl_xor_sync(0xffffffffu, vmin, off));
        }
        if (lane == 0) {
            atomicMax(&g_stats[idxMax], __float_as_int(vmax));
            atomicMin(&g_stats[idxMin], __float_as_int(vmin));
        }
    }
    __syncthreads();
}

// ---------------- kernels ----------------
__global__ void k_init() {
    int t = threadIdx.x;
    if (t < 8) g_stats[t] = (t & 1) ? 0x7f800000 : 0;  // min slots = +inf bits, max slots = 0.0f bits
}

__global__ void k_delta_stats(const float* __restrict__ lat, const float* __restrict__ lon,
                              const float* __restrict__ ut) {
    int b = blockIdx.x;
    const float* la = lat + b * Ll;
    const float* lo = lon + b * Ll;
    const float* u  = ut  + b * Ll;
    float dsmax = -CUDART_INF_F, dsmin = CUDART_INF_F;
    float dtmax = -CUDART_INF_F, dtmin = CUDART_INF_F;
    for (int idx = threadIdx.x; idx < Ll * Ll; idx += blockDim.x) {
        int i = idx / Ll, j = idx % Ll;
        float ds = hav(la[i], lo[i], la[j], lo[j]);
        float dt = fabsf(u[i] - u[j]);
        dsmax = fmaxf(dsmax, ds); dsmin = fminf(dsmin, ds);
        dtmax = fmaxf(dtmax, dt); dtmin = fminf(dtmin, dt);
    }
    blockMinMaxAtomic(dsmax, dsmin, 0, 1);
    blockMinMaxAtomic(dtmax, dtmin, 2, 3);
}

__global__ void k_ti(const float* __restrict__ ut) {
    float vmax = -CUDART_INF_F, vmin = CUDART_INF_F;
    for (int i = threadIdx.x; i < Rr; i += blockDim.x) {
        int l = i % Ll;
        float t = (l == 0) ? 0.0f : fabsf(ut[i] - ut[i - 1]);
        g_ti[i] = t;
        vmax = fmaxf(vmax, t); vmin = fminf(vmin, t);
    }
    blockMinMaxAtomic(vmax, vmin, 6, 7);
}

__global__ void k_dm_stats(const int* __restrict__ poi, const float* __restrict__ dm) {
    long row = poi[blockIdx.x];
    const float* r = dm + row * (long)Pp;
    float vmax = -CUDART_INF_F, vmin = CUDART_INF_F;
    for (int c = threadIdx.x; c < Pp; c += blockDim.x) {
        float v = r[c];
        vmax = fmaxf(vmax, v); vmin = fminf(vmin, v);
    }
    blockMinMaxAtomic(vmax, vmin, 4, 5);
}

__global__ void k_transpose(const float* __restrict__ pw) {
    __shared__ float tile[32][33];
    int pBase = blockIdx.x * 32, fBase = blockIdx.y * 32;
    int x = threadIdx.x, y = threadIdx.y;
    #pragma unroll
    for (int j = 0; j < 4; j++) {
        int p = pBase + y + j * 8;
        tile[y + j * 8][x] = (p < Pp) ? pw[p * Ff + fBase + x] : 0.0f;
    }
    __syncthreads();
    #pragma unroll
    for (int j = 0; j < 4; j++) {
        g_embT[(fBase + y + j * 8) * MP + pBase + x] = tile[x][y + j * 8];
    }
}

__global__ void __launch_bounds__(128) k_attn(
    const int* __restrict__ user, const int* __restrict__ poi,
    const int* __restrict__ tod,  const int* __restrict__ dow,
    const float* __restrict__ lat, const float* __restrict__ lon, const float* __restrict__ ut,
    const float* __restrict__ uw, const float* __restrict__ pw,
    const float* __restrict__ tw, const float* __restrict__ dww,
    const float* __restrict__ Wq, const float* __restrict__ bq,
    const float* __restrict__ Wk, const float* __restrict__ bk,
    const float* __restrict__ Wv, const float* __restrict__ bv) {
    __shared__ float inp_s[Ll][Ff];
    __shared__ float q_s[Ll][132];
    __shared__ float k_s[Ll][132];
    __shared__ float sc[Ll][26];
    int b = blockIdx.x, tid = threadIdx.x;

    // embeddings gather (cat is unused by the reference)
    for (int i = tid; i < Ll * Ff; i += 128) {
        int l = i >> 7, f = i & 127;
        int base = b * Ll + l;
        inp_s[l][f] = uw[user[base] * Ff + f] + pw[poi[base] * Ff + f]
                    + tw[tod[base] * Ff + f]  + dww[dow[base] * Ff + f];
    }
    __syncthreads();

    // qkv: thread = output feature f, accumulators over l
    int f = tid;
    float aq[Ll], ak[Ll], av[Ll];
    #pragma unroll
    for (int l = 0; l < Ll; l++) { aq[l] = 0.f; ak[l] = 0.f; av[l] = 0.f; }
    for (int g = 0; g < Ff; g++) {
        float wq = Wq[g * Ff + f], wk = Wk[g * Ff + f], wv = Wv[g * Ff + f];
        #pragma unroll
        for (int l = 0; l < Ll; l++) {
            float x = inp_s[l][g];
            aq[l] = fmaf(x, wq, aq[l]);
            ak[l] = fmaf(x, wk, ak[l]);
            av[l] = fmaf(x, wv, av[l]);
        }
    }
    {
        float bqf = bq[f], bkf = bk[f], bvf = bv[f];
        #pragma unroll
        for (int l = 0; l < Ll; l++) {
            q_s[l][f] = aq[l] + bqf;
            k_s[l][f] = ak[l] + bkf;
            av[l] += bvf;               // v stays in registers (column f)
        }
    }
    __syncthreads();

    // scores + spatio-temporal delta
    float invDs = 1.0f / (__int_as_float(g_stats[0]) - __int_as_float(g_stats[1]));
    float invDt = 1.0f / (__int_as_float(g_stats[2]) - __int_as_float(g_stats[3]));
    for (int idx = tid; idx < Ll * Ll; idx += 128) {
        int i = idx / Ll, j = idx % Ll;
        float s = 0.f;
        for (int f2 = 0; f2 < Ff; f2++) s = fmaf(q_s[i][f2], k_s[j][f2], s);
        int bi = b * Ll + i, bj = b * Ll + j;
        float ds = hav(lat[bi], lon[bi], lat[bj], lon[bj]);
        float dt = fabsf(ut[bi] - ut[bj]);
        sc[i][j] = s + 0.5f * (__expf(-ds * invDs) + __expf(-dt * invDt));
    }
    __syncthreads();

    // softmax per row
    if (tid < Ll) {
        float m = -CUDART_INF_F;
        for (int j = 0; j < Ll; j++) m = fmaxf(m, sc[tid][j]);
        float sum = 0.f;
        for (int j = 0; j < Ll; j++) sum += __expf(sc[tid][j] - m);
        float inv = 1.0f / sum;
        for (int j = 0; j < Ll; j++) sc[tid][j] = __expf(sc[tid][j] - m) * inv;
    }
    __syncthreads();

    // sao[i,f] = sum_j attn[i,j] * v[j,f]  (v from registers)
    for (int i = 0; i < Ll; i++) {
        float acc = 0.f;
        #pragma unroll
        for (int j = 0; j < Ll; j++) acc = fmaf(sc[i][j], av[j], acc);
        g_sao[(b * Ll + i) * Ff + f] = acc;
    }
}

// M(1600 x 10112) = sao(1600x128) @ embT(128x10112), fp32-accurate via split-bf16 (3 passes)
__global__ void __launch_bounds__(256) k_gemm() {
    __shared__ __nv_bfloat16 AsH[64][40], AsR[64][40];
    __shared__ __nv_bfloat16 BsH[32][136], BsR[32][136];
    int tid = threadIdx.x;
    int rowTile = blockIdx.y * 64, colTile = blockIdx.x * 128;
    int w = tid >> 5, wm = w >> 2, wn = w & 3;   // 2x4 warp grid, 32x32 per warp

    wmma::fragment<wmma::accumulator, 16, 16, 16, float> acc[2][2];
    #pragma unroll
    for (int i = 0; i < 2; i++)
        #pragma unroll
        for (int j = 0; j < 2; j++) wmma::fill_fragment(acc[i][j], 0.0f);

    for (int kc = 0; kc < Ff; kc += 32) {
        for (int i = tid; i < 64 * 32; i += 256) {
            int r = i >> 5, c = i & 31;
            float x = g_sao[(rowTile + r) * Ff + kc + c];
            __nv_bfloat16 h = __float2bfloat16(x);
            AsH[r][c] = h;
            AsR[r][c] = __float2bfloat16(x - __bfloat162float(h));
        }
        for (int i = tid; i < 32 * 128; i += 256) {
            int r = i >> 7, c = i & 127;
            float x = g_embT[(kc + r) * MP + colTile + c];
            __nv_bfloat16 h = __float2bfloat16(x);
            BsH[r][c] = h;
            BsR[r][c] = __float2bfloat16(x - __bfloat162float(h));
        }
        __syncthreads();

        #pragma unroll
        for (int kk = 0; kk < 32; kk += 16) {
            wmma::fragment<wmma::matrix_a, 16, 16, 16, __nv_bfloat16, wmma::row_major> aH[2], aR[2];
            wmma::fragment<wmma::matrix_b, 16, 16, 16, __nv_bfloat16, wmma::row_major> bH[2], bR[2];
            #pragma unroll
            for (int i = 0; i < 2; i++) {
                wmma::load_matrix_sync(aH[i], &AsH[wm * 32 + i * 16][kk], 40);
                wmma::load_matrix_sync(aR[i], &AsR[wm * 32 + i * 16][kk], 40);
            }
            #pragma unroll
            for (int j = 0; j < 2; j++) {
                wmma::load_matrix_sync(bH[j], &BsH[kk][wn * 32 + j * 16], 136);
                wmma::load_matrix_sync(bR[j], &BsR[kk][wn * 32 + j * 16], 136);
            }
            #pragma unroll
            for (int i = 0; i < 2; i++)
                #pragma unroll
                for (int j = 0; j < 2; j++) {
                    wmma::mma_sync(acc[i][j], aH[i], bH[j], acc[i][j]);
                    wmma::mma_sync(acc[i][j], aR[i], bH[j], acc[i][j]);
                    wmma::mma_sync(acc[i][j], aH[i], bR[j], acc[i][j]);
                }
        }
        __syncthreads();
    }
    #pragma unroll
    for (int i = 0; i < 2; i++)
        #pragma unroll
        for (int j = 0; j < 2; j++)
            wmma::store_matrix_sync(
                g_M + (long)(rowTile + wm * 32 + i * 16) * MP + colTile + wn * 32 + j * 16,
                acc[i][j], MP, wmma::mem_row_major);
}

// pre[b,p] = b_val + sum_l 0.5*w[l]*M[b,l,p]*(exp(-dm[poi,p]/S1) + exp(-ti/T1))
__global__ void __launch_bounds__(256) k_final(
    const int* __restrict__ poi, const float* __restrict__ dm,
    const float* __restrict__ wval, const float* __restrict__ bval,
    float* __restrict__ out, int dup) {
    __shared__ int prow[Ll];
    __shared__ float cw[Ll], e2[Ll];
    int b = blockIdx.y, tid = threadIdx.x;
    if (tid < Ll) {
        prow[tid] = poi[b * Ll + tid];
        cw[tid] = 0.5f * wval[tid];
        float T1 = __int_as_float(g_stats[6]) - __int_as_float(g_stats[7]);
        e2[tid] = __expf(-g_ti[b * Ll + tid] / T1);
    }
    __syncthreads();
    int p = blockIdx.x * 256 + tid;
    if (p < Pp) {
        float invS1 = 1.0f / (__int_as_float(g_stats[4]) - __int_as_float(g_stats[5]));
        float acc = bval[0];
        const float* Mrow = g_M + (long)b * Ll * MP + p;
        #pragma unroll
        for (int l = 0; l < Ll; l++) {
            float m = Mrow[l * MP];
            float d = dm[(long)prow[l] * Pp + p];
            acc = fmaf(cw[l] * m, __expf(-d * invS1) + e2[l], acc);
        }
        out[b * Pp + p] = acc;
        if (dup) out[Bb * Pp + b * Pp + p] = acc;
    }
}

// ---------------- launch ----------------
extern "C" void kernel_launch(void* const* d_in, const int* in_sizes, int n_in,
                              void* d_out, int out_size) {
    const int*   user = (const int*)  d_in[0];
    const int*   poi  = (const int*)  d_in[1];
    // d_in[2] = cat (unused by reference)
    const float* lat  = (const float*)d_in[3];
    const float* lon  = (const float*)d_in[4];
    const int*   tod  = (const int*)  d_in[5];
    const int*   dow  = (const int*)  d_in[6];
    const float* ut   = (const float*)d_in[7];
    const float* uw   = (const float*)d_in[8];
    const float* pw   = (const float*)d_in[9];
    const float* tw   = (const float*)d_in[10];
    const float* dww  = (const float*)d_in[11];
    const float* Wq   = (const float*)d_in[12];
    const float* bq   = (const float*)d_in[13];
    const float* Wk   = (const float*)d_in[14];
    const float* bk   = (const float*)d_in[15];
    const float* Wv   = (const float*)d_in[16];
    const float* bv   = (const float*)d_in[17];
    const float* wval = (const float*)d_in[18];
    const float* bval = (const float*)d_in[19];
    const float* dm   = (const float*)d_in[20];
    float* out = (float*)d_out;
    int dup = (out_size >= 2 * Bb * Pp) ? 1 : 0;

    k_init<<<1, 32>>>();
    k_delta_stats<<<Bb, 256>>>(lat, lon, ut);
    k_ti<<<1, 256>>>(ut);
    k_dm_stats<<<Rr, 256>>>(poi, dm);
    k_transpose<<<dim3(316, 4), dim3(32, 8)>>>(pw);
    k_attn<<<Bb, 128>>>(user, poi, tod, dow, lat, lon, ut,
                        uw, pw, tw, dww, Wq, bq, Wk, bk, Wv, bv);
    k_gemm<<<dim3(79, 25), 256>>>();
    k_final<<<dim3(40, Bb), 256>>>(poi, dm, wval, bval, out, dup);
}

// round 5
// speedup vs baseline: 1.3625x; 1.3625x over previous
#include <cuda_runtime.h>
#include <cuda_bf16.h>
#include <mma.h>
#include <math_constants.h>

using namespace nvcuda;

// Problem dims
#define Bb   64
#define Ll   25
#define Ff   128
#define Pp   10000
#define Rr   (Bb*Ll)        // 1600 rows

// ---------------- device scratch ----------------
// stats layout (int bits of nonnegative floats):
// 0 ds_max, 1 ds_min, 2 dt_max, 3 dt_min, 4 is_max, 5 is_min, 6 ti_max, 7 ti_min
__device__ int   g_stats[8];
__device__ float g_ti[Rr];
__device__ float g_q[Rr * Ff];
__device__ float g_k[Rr * Ff];
__device__ float g_v[Rr * Ff];
__device__ float g_sao[Rr * Ff];

// ---------------- helpers ----------------
__device__ __forceinline__ float hav(float lat1, float lon1, float lat2, float lon2) {
    const float pc = 0.017453292519943295f;  // pi/180
    float a = 0.5f - cosf((lat2 - lat1) * pc) * 0.5f
            + cosf(lat1 * pc) * cosf(lat2 * pc) * (1.0f - cosf((lon2 - lon1) * pc)) * 0.5f;
    a = fminf(fmaxf(a, 0.0f), 1.0f);
    return 12742.0f * asinf(sqrtf(a));
}

__device__ __forceinline__ void blockMinMaxAtomic(float vmax, float vmin, int idxMax, int idxMin) {
    #pragma unroll
    for (int off = 16; off; off >>= 1) {
        vmax = fmaxf(vmax, __shfl_xor_sync(0xffffffffu, vmax, off));
        vmin = fminf(vmin, __shfl_xor_sync(0xffffffffu, vmin, off));
    }
    __shared__ float smax[8], smin[8];
    int warp = threadIdx.x >> 5, lane = threadIdx.x & 31;
    int nw = (blockDim.x + 31) >> 5;
    if (lane == 0) { smax[warp] = vmax; smin[warp] = vmin; }
    __syncthreads();
    if (warp == 0) {
        vmax = (lane < nw) ? smax[lane] : -CUDART_INF_F;
        vmin = (lane < nw) ? smin[lane] :  CUDART_INF_F;
        #pragma unroll
        for (int off = 4; off; off >>= 1) {
            vmax = fmaxf(vmax, __shfl_xor_sync(0xffffffffu, vmax, off));
            vmin = fminf(vmin, __shfl_xor_sync(0xffffffffu, vmin, off));
        }
        if (lane == 0) {
            atomicMax(&g_stats[idxMax], __float_as_int(vmax));
            atomicMin(&g_stats[idxMin], __float_as_int(vmin));
        }
    }
    __syncthreads();
}

// ---------------- kernels ----------------
__global__ void k_init() {
    int t = threadIdx.x;
    if (t < 8) g_stats[t] = (t & 1) ? 0x7f800000 : 0;
}

__global__ void k_delta_stats(const float* __restrict__ lat, const float* __restrict__ lon,
                              const float* __restrict__ ut) {
    int b = blockIdx.x;
    const float* la = lat + b * Ll;
    const float* lo = lon + b * Ll;
    const float* u  = ut  + b * Ll;
    float dsmax = -CUDART_INF_F, dsmin = CUDART_INF_F;
    float dtmax = -CUDART_INF_F, dtmin = CUDART_INF_F;
    for (int idx = threadIdx.x; idx < Ll * Ll; idx += blockDim.x) {
        int i = idx / Ll, j = idx % Ll;
        float ds = hav(la[i], lo[i], la[j], lo[j]);
        float dt = fabsf(u[i] - u[j]);
        dsmax = fmaxf(dsmax, ds); dsmin = fminf(dsmin, ds);
        dtmax = fmaxf(dtmax, dt); dtmin = fminf(dtmin, dt);
    }
    blockMinMaxAtomic(dsmax, dsmin, 0, 1);
    blockMinMaxAtomic(dtmax, dtmin, 2, 3);
}

__global__ void k_ti(const float* __restrict__ ut) {
    float vmax = -CUDART_INF_F, vmin = CUDART_INF_F;
    for (int i = threadIdx.x; i < Rr; i += blockDim.x) {
        int l = i % Ll;
        float t = (l == 0) ? 0.0f : fabsf(ut[i] - ut[i - 1]);
        g_ti[i] = t;
        vmax = fmaxf(vmax, t); vmin = fminf(vmin, t);
    }
    blockMinMaxAtomic(vmax, vmin, 6, 7);
}

// float4 pass over 1600 gathered dm rows (also warms L2 for the fused epilogue)
__global__ void k_dm_stats(const int* __restrict__ poi, const float* __restrict__ dm) {
    long row = poi[blockIdx.x];
    const float4* r = (const float4*)(dm + row * (long)Pp);
    float vmax = -CUDART_INF_F, vmin = CUDART_INF_F;
    for (int c = threadIdx.x; c < Pp / 4; c += blockDim.x) {
        float4 v = __ldg(&r[c]);
        vmax = fmaxf(vmax, fmaxf(fmaxf(v.x, v.y), fmaxf(v.z, v.w)));
        vmin = fminf(vmin, fminf(fminf(v.x, v.y), fminf(v.z, v.w)));
    }
    blockMinMaxAtomic(vmax, vmin, 4, 5);
}

// grid (Bb, 2): each block computes q,k,v for ~half the L rows of one batch
__global__ void __launch_bounds__(128) k_qkv(
    const int* __restrict__ user, const int* __restrict__ poi,
    const int* __restrict__ tod,  const int* __restrict__ dow,
    const float* __restrict__ uw, const float* __restrict__ pw,
    const float* __restrict__ tw, const float* __restrict__ dww,
    const float* __restrict__ Wq, const float* __restrict__ bq,
    const float* __restrict__ Wk, const float* __restrict__ bk,
    const float* __restrict__ Wv, const float* __restrict__ bv) {
    __shared__ float inp_s[13][Ff];
    int b = blockIdx.x, half = blockIdx.y, tid = threadIdx.x;
    int l0 = half * 13;
    int nl = half ? 12 : 13;

    for (int i = tid; i < 13 * Ff; i += 128) {
        int l = i >> 7, f = i & 127;
        float v = 0.0f;
        if (l0 + l < Ll) {
            int base = b * Ll + l0 + l;
            v = uw[user[base] * Ff + f] + pw[poi[base] * Ff + f]
              + tw[tod[base] * Ff + f]  + dww[dow[base] * Ff + f];
        }
        inp_s[l][f] = v;
    }
    __syncthreads();

    int f = tid;
    float aq[13], ak[13], av[13];
    #pragma unroll
    for (int l = 0; l < 13; l++) { aq[l] = 0.f; ak[l] = 0.f; av[l] = 0.f; }
    for (int g = 0; g < Ff; g++) {
        float wq = Wq[g * Ff + f], wk = Wk[g * Ff + f], wv = Wv[g * Ff + f];
        #pragma unroll
        for (int l = 0; l < 13; l++) {
            float x = inp_s[l][g];
            aq[l] = fmaf(x, wq, aq[l]);
            ak[l] = fmaf(x, wk, ak[l]);
            av[l] = fmaf(x, wv, av[l]);
        }
    }
    float bqf = bq[f], bkf = bk[f], bvf = bv[f];
    #pragma unroll
    for (int l = 0; l < 13; l++) {
        if (l < nl) {
            int ridx = (b * Ll + l0 + l) * Ff + f;
            g_q[ridx] = aq[l] + bqf;
            g_k[ridx] = ak[l] + bkf;
            g_v[ridx] = av[l] + bvf;
        }
    }
}

// grid Bb: scores + delta + softmax + attn@v
__global__ void __launch_bounds__(128) k_attn2(
    const float* __restrict__ lat, const float* __restrict__ lon, const float* __restrict__ ut) {
    __shared__ float q_s[Ll][132];
    __shared__ float k_s[Ll][132];
    __shared__ float sc[Ll][26];
    int b = blockIdx.x, tid = threadIdx.x;

    for (int i = tid; i < Ll * Ff; i += 128) {
        int l = i >> 7, f = i & 127;
        q_s[l][f] = g_q[(b * Ll + l) * Ff + f];
        k_s[l][f] = g_k[(b * Ll + l) * Ff + f];
    }
    int f = tid;
    float av[Ll];
    #pragma unroll
    for (int l = 0; l < Ll; l++) av[l] = g_v[(b * Ll + l) * Ff + f];
    __syncthreads();

    float invDs = 1.0f / (__int_as_float(g_stats[0]) - __int_as_float(g_stats[1]));
    float invDt = 1.0f / (__int_as_float(g_stats[2]) - __int_as_float(g_stats[3]));
    for (int idx = tid; idx < Ll * Ll; idx += 128) {
        int i = idx / Ll, j = idx % Ll;
        float s = 0.f;
        #pragma unroll 16
        for (int f2 = 0; f2 < Ff; f2++) s = fmaf(q_s[i][f2], k_s[j][f2], s);
        int bi = b * Ll + i, bj = b * Ll + j;
        float ds = hav(lat[bi], lon[bi], lat[bj], lon[bj]);
        float dt = fabsf(ut[bi] - ut[bj]);
        sc[i][j] = s + 0.5f * (__expf(-ds * invDs) + __expf(-dt * invDt));
    }
    __syncthreads();

    if (tid < Ll) {
        float m = -CUDART_INF_F;
        for (int j = 0; j < Ll; j++) m = fmaxf(m, sc[tid][j]);
        float sum = 0.f;
        for (int j = 0; j < Ll; j++) sum += __expf(sc[tid][j] - m);
        float inv = 1.0f / sum;
        for (int j = 0; j < Ll; j++) sc[tid][j] = __expf(sc[tid][j] - m) * inv;
    }
    __syncthreads();

    for (int i = 0; i < Ll; i++) {
        float acc = 0.f;
        #pragma unroll
        for (int j = 0; j < Ll; j++) acc = fmaf(sc[i][j], av[j], acc);
        g_sao[(b * Ll + i) * Ff + f] = acc;
    }
}

// Fused: S(64x128) = sao(2 batches, padded 25->32 rows) @ pw^T tile, split-bf16 3-pass,
// then epilogue out[b,p] = bval + sum_l 0.5*w[l]*S[l,p]*(exp(-dm[poi,p]/S1)+exp(-ti/T1))
// dynamic smem: AsH/AsR 64x136 bf16, BsH/BsR 128x136 bf16 = 104448 B; S(fp32 64x128) aliases A region.
#define SMEM_FUSED 104448

__global__ void __launch_bounds__(128) k_fused(
    const int* __restrict__ poi, const float* __restrict__ pw,
    const float* __restrict__ dm, const float* __restrict__ wval,
    const float* __restrict__ bval, float* __restrict__ out, int dup) {
    extern __shared__ char smraw[];
    __nv_bfloat16* AsH = (__nv_bfloat16*)smraw;
    __nv_bfloat16* AsR = AsH + 64 * 136;
    __nv_bfloat16* BsH = AsR + 64 * 136;
    __nv_bfloat16* BsR = BsH + 128 * 136;
    float* S = (float*)smraw;               // 64*128 fp32 = 32KB, overlays A region (34KB)
    __shared__ int   prow[2][Ll];
    __shared__ float cw[Ll], e2[2][Ll];

    int tid = threadIdx.x;
    int colTile = blockIdx.x * 128;
    int b0 = blockIdx.y * 2;

    if (tid < 2 * Ll) {
        int batch = tid / Ll, l = tid % Ll;
        int b = b0 + batch;
        prow[batch][l] = poi[b * Ll + l];
        float T1 = __int_as_float(g_stats[6]) - __int_as_float(g_stats[7]);
        e2[batch][l] = __expf(-g_ti[b * Ll + l] / T1);
        if (batch == 0) cw[l] = 0.5f * wval[l];
    }

    // stage A: 64 rows (2 batches x 32, rows 25..31 zero) x 128 k
    for (int i = tid; i < 64 * 32; i += 128) {
        int r = i >> 5, c4 = (i & 31) << 2;
        int l = r & 31;
        float4 v = make_float4(0.f, 0.f, 0.f, 0.f);
        if (l < Ll) v = *(const float4*)(g_sao + ((b0 + (r >> 5)) * Ll + l) * Ff + c4);
        int o = r * 136 + c4;
        float xs[4] = {v.x, v.y, v.z, v.w};
        #pragma unroll
        for (int k = 0; k < 4; k++) {
            __nv_bfloat16 h = __float2bfloat16(xs[k]);
            AsH[o + k] = h;
            AsR[o + k] = __float2bfloat16(xs[k] - __bfloat162float(h));
        }
    }
    // stage B: 128 p-rows x 128 k straight from poi_emb_w (col_major frags -> no transpose)
    for (int i = tid; i < 128 * 32; i += 128) {
        int r = i >> 5, c4 = (i & 31) << 2;
        int p = colTile + r;
        float4 v = make_float4(0.f, 0.f, 0.f, 0.f);
        if (p < Pp) v = *(const float4*)(pw + (long)p * Ff + c4);
        int o = r * 136 + c4;
        float xs[4] = {v.x, v.y, v.z, v.w};
        #pragma unroll
        for (int k = 0; k < 4; k++) {
            __nv_bfloat16 h = __float2bfloat16(xs[k]);
            BsH[o + k] = h;
            BsR[o + k] = __float2bfloat16(xs[k] - __bfloat162float(h));
        }
    }
    __syncthreads();

    int w = tid >> 5, wm = w >> 1, wn = w & 1;   // 2x2 warps, each 32 rows x 64 cols
    wmma::fragment<wmma::accumulator, 16, 16, 16, float> acc[2][4];
    #pragma unroll
    for (int i = 0; i < 2; i++)
        #pragma unroll
        for (int j = 0; j < 4; j++) wmma::fill_fragment(acc[i][j], 0.0f);

    #pragma unroll
    for (int kk = 0; kk < Ff; kk += 16) {
        wmma::fragment<wmma::matrix_a, 16, 16, 16, __nv_bfloat16, wmma::row_major> aH[2], aR[2];
        wmma::fragment<wmma::matrix_b, 16, 16, 16, __nv_bfloat16, wmma::col_major> bH[4], bR[4];
        #pragma unroll
        for (int i = 0; i < 2; i++) {
            wmma::load_matrix_sync(aH[i], AsH + (wm * 32 + i * 16) * 136 + kk, 136);
            wmma::load_matrix_sync(aR[i], AsR + (wm * 32 + i * 16) * 136 + kk, 136);
        }
        #pragma unroll
        for (int j = 0; j < 4; j++) {
            wmma::load_matrix_sync(bH[j], BsH + (wn * 64 + j * 16) * 136 + kk, 136);
            wmma::load_matrix_sync(bR[j], BsR + (wn * 64 + j * 16) * 136 + kk, 136);
        }
        #pragma unroll
        for (int i = 0; i < 2; i++)
            #pragma unroll
            for (int j = 0; j < 4; j++) {
                wmma::mma_sync(acc[i][j], aH[i], bH[j], acc[i][j]);
                wmma::mma_sync(acc[i][j], aR[i], bH[j], acc[i][j]);
                wmma::mma_sync(acc[i][j], aH[i], bR[j], acc[i][j]);
            }
    }
    __syncthreads();   // all frag reads done before S overlays A region

    #pragma unroll
    for (int i = 0; i < 2; i++)
        #pragma unroll
        for (int j = 0; j < 4; j++)
            wmma::store_matrix_sync(S + (wm * 32 + i * 16) * 128 + wn * 64 + j * 16,
                                    acc[i][j], 128, wmma::mem_row_major);
    __syncthreads();

    // epilogue: thread = one p column, reduce over l for both batches
    int p = colTile + tid;
    if (p < Pp) {
        float invS1 = 1.0f / (__int_as_float(g_stats[4]) - __int_as_float(g_stats[5]));
        float bv0 = bval[0];
        #pragma unroll
        for (int batch = 0; batch < 2; batch++) {
            float a2 = bv0;
            #pragma unroll
            for (int l = 0; l < Ll; l++) {
                float m = S[(batch * 32 + l) * 128 + tid];
                float d = dm[(long)prow[batch][l] * Pp + p];
                a2 = fmaf(cw[l] * m, __expf(-d * invS1) + e2[batch][l], a2);
            }
            int b = b0 + batch;
            out[b * Pp + p] = a2;
            if (dup) out[Bb * Pp + b * Pp + p] = a2;
        }
    }
}

// ---------------- launch ----------------
extern "C" void kernel_launch(void* const* d_in, const int* in_sizes, int n_in,
                              void* d_out, int out_size) {
    const int*   user = (const int*)  d_in[0];
    const int*   poi  = (const int*)  d_in[1];
    // d_in[2] = cat (unused by reference)
    const float* lat  = (const float*)d_in[3];
    const float* lon  = (const float*)d_in[4];
    const int*   tod  = (const int*)  d_in[5];
    const int*   dow  = (const int*)  d_in[6];
    const float* ut   = (const float*)d_in[7];
    const float* uw   = (const float*)d_in[8];
    const float* pw   = (const float*)d_in[9];
    const float* tw   = (const float*)d_in[10];
    const float* dww  = (const float*)d_in[11];
    const float* Wq   = (const float*)d_in[12];
    const float* bq   = (const float*)d_in[13];
    const float* Wk   = (const float*)d_in[14];
    const float* bk   = (const float*)d_in[15];
    const float* Wv   = (const float*)d_in[16];
    const float* bv   = (const float*)d_in[17];
    const float* wval = (const float*)d_in[18];
    const float* bval = (const float*)d_in[19];
    const float* dm   = (const float*)d_in[20];
    float* out = (float*)d_out;
    int dup = (out_size >= 2 * Bb * Pp) ? 1 : 0;

    cudaFuncSetAttribute(k_fused, cudaFuncAttributeMaxDynamicSharedMemorySize, SMEM_FUSED);

    k_init<<<1, 32>>>();
    k_delta_stats<<<Bb, 256>>>(lat, lon, ut);
    k_ti<<<1, 256>>>(ut);
    k_qkv<<<dim3(Bb, 2), 128>>>(user, poi, tod, dow, uw, pw, tw, dww,
                                Wq, bq, Wk, bk, Wv, bv);
    k_attn2<<<Bb, 128>>>(lat, lon, ut);
    k_dm_stats<<<Rr, 256>>>(poi, dm);           // right before k_fused: dm rows L2-hot
    k_fused<<<dim3(79, Bb / 2), 128, SMEM_FUSED>>>(poi, pw, dm, wval, bval, out, dup);
}

// round 7
// speedup vs baseline: 1.3967x; 1.0251x over previous
#include <cuda_runtime.h>
#include <cuda_bf16.h>
#include <mma.h>
#include <math_constants.h>

using namespace nvcuda;

// Problem dims
#define Bb   64
#define Ll   25
#define Ff   128
#define Pp   10000
#define Rr   (Bb*Ll)        // 1600 rows

// ---------------- device scratch ----------------
// stats layout (int bits of nonnegative floats):
// 0 ds_max, 1 ds_min, 2 dt_max, 3 dt_min, 4 is_max, 5 is_min, 6 ti_max, 7 ti_min
__device__ int   g_stats[8];
__device__ float g_ti[Rr];
__device__ float g_q[Rr * Ff];
__device__ float g_k[Rr * Ff];
__device__ float g_v[Rr * Ff];
__device__ __nv_bfloat16 g_saoH[Rr * Ff];
__device__ __nv_bfloat16 g_saoR[Rr * Ff];
__device__ __nv_bfloat16 g_pwH[Pp * Ff];   // 2.56 MB
__device__ __nv_bfloat16 g_pwR[Pp * Ff];   // 2.56 MB

// ---------------- helpers ----------------
__device__ __forceinline__ float hav(float lat1, float lon1, float lat2, float lon2) {
    const float pc = 0.017453292519943295f;  // pi/180
    float a = 0.5f - cosf((lat2 - lat1) * pc) * 0.5f
            + cosf(lat1 * pc) * cosf(lat2 * pc) * (1.0f - cosf((lon2 - lon1) * pc)) * 0.5f;
    a = fminf(fmaxf(a, 0.0f), 1.0f);
    return 12742.0f * asinf(sqrtf(a));
}

__device__ __forceinline__ void blockMinMaxAtomic(float vmax, float vmin, int idxMax, int idxMin) {
    #pragma unroll
    for (int off = 16; off; off >>= 1) {
        vmax = fmaxf(vmax, __shfl_xor_sync(0xffffffffu, vmax, off));
        vmin = fminf(vmin, __shfl_xor_sync(0xffffffffu, vmin, off));
    }
    __shared__ float smax[8], smin[8];
    int warp = threadIdx.x >> 5, lane = threadIdx.x & 31;
    int nw = (blockDim.x + 31) >> 5;
    if (lane == 0) { smax[warp] = vmax; smin[warp] = vmin; }
    __syncthreads();
    if (warp == 0) {
        vmax = (lane < nw) ? smax[lane] : -CUDART_INF_F;
        vmin = (lane < nw) ? smin[lane] :  CUDART_INF_F;
        #pragma unroll
        for (int off = 4; off; off >>= 1) {
            vmax = fmaxf(vmax, __shfl_xor_sync(0xffffffffu, vmax, off));
            vmin = fminf(vmin, __shfl_xor_sync(0xffffffffu, vmin, off));
        }
        if (lane == 0) {
            atomicMax(&g_stats[idxMax], __float_as_int(vmax));
            atomicMin(&g_stats[idxMin], __float_as_int(vmin));
        }
    }
    __syncthreads();
}

// ---------------- kernels ----------------
__global__ void k_init() {
    int t = threadIdx.x;
    if (t < 8) g_stats[t] = (t & 1) ? 0x7f800000 : 0;
}

// split poi_emb_w into bf16 hi/res once
__global__ void __launch_bounds__(256) k_prep(const float* __restrict__ pw) {
    int i = blockIdx.x * 256 + threadIdx.x;           // one float4 per thread
    if (i < Pp * Ff / 4) {
        float4 v = ((const float4*)pw)[i];
        float xs[4] = {v.x, v.y, v.z, v.w};
        #pragma unroll
        for (int k = 0; k < 4; k++) {
            __nv_bfloat16 h = __float2bfloat16(xs[k]);
            g_pwH[i * 4 + k] = h;
            g_pwR[i * 4 + k] = __float2bfloat16(xs[k] - __bfloat162float(h));
        }
    }
}

__global__ void k_delta_stats(const float* __restrict__ lat, const float* __restrict__ lon,
                              const float* __restrict__ ut) {
    int b = blockIdx.x;
    const float* la = lat + b * Ll;
    const float* lo = lon + b * Ll;
    const float* u  = ut  + b * Ll;
    float dsmax = -CUDART_INF_F, dsmin = CUDART_INF_F;
    float dtmax = -CUDART_INF_F, dtmin = CUDART_INF_F;
    for (int idx = threadIdx.x; idx < Ll * Ll; idx += blockDim.x) {
        int i = idx / Ll, j = idx % Ll;
        float ds = hav(la[i], lo[i], la[j], lo[j]);
        float dt = fabsf(u[i] - u[j]);
        dsmax = fmaxf(dsmax, ds); dsmin = fminf(dsmin, ds);
        dtmax = fmaxf(dtmax, dt); dtmin = fminf(dtmin, dt);
    }
    blockMinMaxAtomic(dsmax, dsmin, 0, 1);
    blockMinMaxAtomic(dtmax, dtmin, 2, 3);
}

__global__ void k_ti(const float* __restrict__ ut) {
    float vmax = -CUDART_INF_F, vmin = CUDART_INF_F;
    for (int i = threadIdx.x; i < Rr; i += blockDim.x) {
        int l = i % Ll;
        float t = (l == 0) ? 0.0f : fabsf(ut[i] - ut[i - 1]);
        g_ti[i] = t;
        vmax = fmaxf(vmax, t); vmin = fminf(vmin, t);
    }
    blockMinMaxAtomic(vmax, vmin, 6, 7);
}

// float4 pass over 1600 gathered dm rows (also warms L2 for the fused epilogue)
__global__ void k_dm_stats(const int* __restrict__ poi, const float* __restrict__ dm) {
    long row = poi[blockIdx.x];
    const float4* r = (const float4*)(dm + row * (long)Pp);
    float vmax = -CUDART_INF_F, vmin = CUDART_INF_F;
    for (int c = threadIdx.x; c < Pp / 4; c += blockDim.x) {
        float4 v = __ldg(&r[c]);
        vmax = fmaxf(vmax, fmaxf(fmaxf(v.x, v.y), fmaxf(v.z, v.w)));
        vmin = fminf(vmin, fminf(fminf(v.x, v.y), fminf(v.z, v.w)));
    }
    blockMinMaxAtomic(vmax, vmin, 4, 5);
}

// grid (Bb, 2, 3): block computes ONE of q/k/v for ~half the L rows of one batch.
// 13 accumulators/thread -> registers free for load pipelining (the old 39-acc
// version was latency-bound at 64 regs / MLP~1).
__global__ void __launch_bounds__(128) k_qkv(
    const int* __restrict__ user, const int* __restrict__ poi,
    const int* __restrict__ tod,  const int* __restrict__ dow,
    const float* __restrict__ uw, const float* __restrict__ pw,
    const float* __restrict__ tw, const float* __restrict__ dww,
    const float* __restrict__ Wq, const float* __restrict__ bq,
    const float* __restrict__ Wk, const float* __restrict__ bk,
    const float* __restrict__ Wv, const float* __restrict__ bv) {
    __shared__ float inp_s[13][Ff];
    int b = blockIdx.x, half = blockIdx.y, z = blockIdx.z, tid = threadIdx.x;
    int l0 = half * 13;
    int nl = half ? 12 : 13;

    for (int i = tid; i < 13 * Ff; i += 128) {
        int l = i >> 7, f = i & 127;
        float v = 0.0f;
        if (l < nl) {
            int base = b * Ll + l0 + l;
            v = uw[user[base] * Ff + f] + pw[poi[base] * Ff + f]
              + tw[tod[base] * Ff + f]  + dww[dow[base] * Ff + f];
        }
        inp_s[l][f] = v;
    }
    __syncthreads();

    const float* W    = (z == 0) ? Wq : (z == 1) ? Wk : Wv;
    const float* bias = (z == 0) ? bq : (z == 1) ? bk : bv;
    float*       dst  = (z == 0) ? g_q : (z == 1) ? g_k : g_v;

    int f = tid;
    float a[13];
    #pragma unroll
    for (int l = 0; l < 13; l++) a[l] = 0.f;
    #pragma unroll 4
    for (int g = 0; g < Ff; g++) {
        float w = W[g * Ff + f];
        #pragma unroll
        for (int l = 0; l < 13; l++) a[l] = fmaf(inp_s[l][g], w, a[l]);
    }
    float bf = bias[f];
    #pragma unroll
    for (int l = 0; l < 13; l++)
        if (l < nl) dst[(b * Ll + l0 + l) * Ff + f] = a[l] + bf;
}

// grid Bb: scores + delta + softmax + attn@v; emits split-bf16 sao directly
__global__ void __launch_bounds__(128) k_attn2(
    const float* __restrict__ lat, const float* __restrict__ lon, const float* __restrict__ ut) {
    __shared__ float q_s[Ll][132];
    __shared__ float k_s[Ll][132];
    __shared__ float sc[Ll][26];
    int b = blockIdx.x, tid = threadIdx.x;

    for (int i = tid; i < Ll * Ff; i += 128) {
        int l = i >> 7, f = i & 127;
        q_s[l][f] = g_q[(b * Ll + l) * Ff + f];
        k_s[l][f] = g_k[(b * Ll + l) * Ff + f];
    }
    int f = tid;
    float av[Ll];
    #pragma unroll
    for (int l = 0; l < Ll; l++) av[l] = g_v[(b * Ll + l) * Ff + f];
    __syncthreads();

    float invDs = 1.0f / (__int_as_float(g_stats[0]) - __int_as_float(g_stats[1]));
    float invDt = 1.0f / (__int_as_float(g_stats[2]) - __int_as_float(g_stats[3]));
    for (int idx = tid; idx < Ll * Ll; idx += 128) {
        int i = idx / Ll, j = idx % Ll;
        float s0 = 0.f, s1 = 0.f, s2 = 0.f, s3 = 0.f;   // 4 chains: latency /4
        #pragma unroll 8
        for (int f2 = 0; f2 < Ff; f2 += 4) {
            s0 = fmaf(q_s[i][f2 + 0], k_s[j][f2 + 0], s0);
            s1 = fmaf(q_s[i][f2 + 1], k_s[j][f2 + 1], s1);
            s2 = fmaf(q_s[i][f2 + 2], k_s[j][f2 + 2], s2);
            s3 = fmaf(q_s[i][f2 + 3], k_s[j][f2 + 3], s3);
        }
        float s = (s0 + s1) + (s2 + s3);
        int bi = b * Ll + i, bj = b * Ll + j;
        float ds = hav(lat[bi], lon[bi], lat[bj], lon[bj]);
        float dt = fabsf(ut[bi] - ut[bj]);
        sc[i][j] = s + 0.5f * (__expf(-ds * invDs) + __expf(-dt * invDt));
    }
    __syncthreads();

    if (tid < Ll) {
        float m = -CUDART_INF_F;
        for (int j = 0; j < Ll; j++) m = fmaxf(m, sc[tid][j]);
        float sum = 0.f;
        for (int j = 0; j < Ll; j++) sum += __expf(sc[tid][j] - m);
        float inv = 1.0f / sum;
        for (int j = 0; j < Ll; j++) sc[tid][j] = __expf(sc[tid][j] - m) * inv;
    }
    __syncthreads();

    for (int i = 0; i < Ll; i++) {
        float acc = 0.f;
        #pragma unroll
        for (int j = 0; j < Ll; j++) acc = fmaf(sc[i][j], av[j], acc);
        int idx = (b * Ll + i) * Ff + f;
        __nv_bfloat16 h = __float2bfloat16(acc);
        g_saoH[idx] = h;
        g_saoR[idx] = __float2bfloat16(acc - __bfloat162float(h));
    }
}

// Fused: S(128x128) = sao(4 batches, padded 25->32 rows) @ pw^T tile, split-bf16 3-pass,
// then epilogue out[b,p] = bval + sum_l 0.5*w[l]*S[l,p]*(exp(-dm[poi,p]/S1)+exp(-ti/T1))
// dyn smem: AsH/AsR 128x136 bf16 + BsH/BsR 128x136 bf16 = 139264 B;
// S(fp32 128x128 = 64KB) overlays the A region (69632 B).
#define SMEM_FUSED 139264

__global__ void __launch_bounds__(256) k_fused(
    const int* __restrict__ poi,
    const float* __restrict__ dm, const float* __restrict__ wval,
    const float* __restrict__ bval, float* __restrict__ out, int dup) {
    extern __shared__ char smraw[];
    __nv_bfloat16* AsH = (__nv_bfloat16*)smraw;
    __nv_bfloat16* AsR = AsH + 128 * 136;
    __nv_bfloat16* BsH = AsR + 128 * 136;
    __nv_bfloat16* BsR = BsH + 128 * 136;
    float* S = (float*)smraw;               // overlays AsH/AsR after MMA
    __shared__ int   prow[4][Ll];
    __shared__ float cw[Ll], e2[4][Ll];

    int tid = threadIdx.x;
    int colTile = blockIdx.x * 128;
    int b0 = blockIdx.y * 4;

    if (tid < 4 * Ll) {
        int bt = tid / Ll, l = tid % Ll;
        int b = b0 + bt;
        prow[bt][l] = poi[b * Ll + l];
        float T1 = __int_as_float(g_stats[6]) - __int_as_float(g_stats[7]);
        e2[bt][l] = __expf(-g_ti[b * Ll + l] / T1);
        if (bt == 0) cw[l] = 0.5f * wval[l];
    }

    // stage A: 128 rows (4 batches x 32, rows 25..31 zero), uint4 = 8 bf16
    for (int i = tid; i < 128 * 16; i += 256) {
        int r = i >> 4, c8 = (i & 15) << 3;
        int bt = r >> 5, l = r & 31;
        uint4 vH = make_uint4(0, 0, 0, 0), vR = make_uint4(0, 0, 0, 0);
        if (l < Ll) {
            long off = ((long)(b0 + bt) * Ll + l) * Ff + c8;
            vH = *(const uint4*)(g_saoH + off);
            vR = *(const uint4*)(g_saoR + off);
        }
        *(uint4*)(AsH + r * 136 + c8) = vH;
        *(uint4*)(AsR + r * 136 + c8) = vR;
    }
    // stage B: 128 p-rows from pre-split pw (col_major frags later -> no transpose)
    for (int i = tid; i < 128 * 16; i += 256) {
        int r = i >> 4, c8 = (i & 15) << 3;
        int p = colTile + r;
        uint4 vH = make_uint4(0, 0, 0, 0), vR = make_uint4(0, 0, 0, 0);
        if (p < Pp) {
            long off = (long)p * Ff + c8;
            vH = *(const uint4*)(g_pwH + off);
            vR = *(const uint4*)(g_pwR + off);
        }
        *(uint4*)(BsH + r * 136 + c8) = vH;
        *(uint4*)(BsR + r * 136 + c8) = vR;
    }
    __syncthreads();

    int w = tid >> 5, wm = w >> 1, wn = w & 1;   // 4x2 warps: each 32 rows x 64 cols
    wmma::fragment<wmma::accumulator, 16, 16, 16, float> acc[2][4];
    #pragma unroll
    for (int i = 0; i < 2; i++)
        #pragma unroll
        for (int j = 0; j < 4; j++) wmma::fill_fragment(acc[i][j], 0.0f);

    #pragma unroll
    for (int kk = 0; kk < Ff; kk += 16) {
        wmma::fragment<wmma::matrix_a, 16, 16, 16, __nv_bfloat16, wmma::row_major> aH[2], aR[2];
        wmma::fragment<wmma::matrix_b, 16, 16, 16, __nv_bfloat16, wmma::col_major> bH[4], bR[4];
        #pragma unroll
        for (int i = 0; i < 2; i++) {
            wmma::load_matrix_sync(aH[i], AsH + (wm * 32 + i * 16) * 136 + kk, 136);
            wmma::load_matrix_sync(aR[i], AsR + (wm * 32 + i * 16) * 136 + kk, 136);
        }
        #pragma unroll
        for (int j = 0; j < 4; j++) {
            wmma::load_matrix_sync(bH[j], BsH + (wn * 64 + j * 16) * 136 + kk, 136);
            wmma::load_matrix_sync(bR[j], BsR + (wn * 64 + j * 16) * 136 + kk, 136);
        }
        #pragma unroll
        for (int i = 0; i < 2; i++)
            #pragma unroll
            for (int j = 0; j < 4; j++) {
                wmma::mma_sync(acc[i][j], aH[i], bH[j], acc[i][j]);
                wmma::mma_sync(acc[i][j], aR[i], bH[j], acc[i][j]);
                wmma::mma_sync(acc[i][j], aH[i], bR[j], acc[i][j]);
            }
    }
    __syncthreads();   // all frag reads done before S overlays A region

    #pragma unroll
    for (int i = 0; i < 2; i++)
        #pragma unroll
        for (int j = 0; j < 4; j++)
            wmma::store_matrix_sync(S + (wm * 32 + i * 16) * 128 + wn * 64 + j * 16,
                                    acc[i][j], 128, wmma::mem_row_major);
    __syncthreads();

    // epilogue: thread = (p column, batch-pair); reduce over l
    int col = tid & 127, bg = tid >> 7;
    int p = colTile + col;
    if (p < Pp) {
        float invS1 = 1.0f / (__int_as_float(g_stats[4]) - __int_as_float(g_stats[5]));
        float bv0 = bval[0];
        #pragma unroll
        for (int bt2 = 0; bt2 < 2; bt2++) {
            int bt = bg * 2 + bt2;
            float a2 = bv0;
            #pragma unroll
            for (int l = 0; l < Ll; l++) {
                float m = S[(bt * 32 + l) * 128 + col];
                float d = dm[(long)prow[bt][l] * Pp + p];
                a2 = fmaf(cw[l] * m, __expf(-d * invS1) + e2[bt][l], a2);
            }
            int b = b0 + bt;
            out[b * Pp + p] = a2;
            if (dup) out[Bb * Pp + b * Pp + p] = a2;
        }
    }
}

// ---------------- launch ----------------
extern "C" void kernel_launch(void* const* d_in, const int* in_sizes, int n_in,
                              void* d_out, int out_size) {
    const int*   user = (const int*)  d_in[0];
    const int*   poi  = (const int*)  d_in[1];
    // d_in[2] = cat (unused by reference)
    const float* lat  = (const float*)d_in[3];
    const float* lon  = (const float*)d_in[4];
    const int*   tod  = (const int*)  d_in[5];
    const int*   dow  = (const int*)  d_in[6];
    const float* ut   = (const float*)d_in[7];
    const float* uw   = (const float*)d_in[8];
    const float* pw   = (const float*)d_in[9];
    const float* tw   = (const float*)d_in[10];
    const float* dww  = (const float*)d_in[11];
    const float* Wq   = (const float*)d_in[12];
    const float* bq   = (const float*)d_in[13];
    const float* Wk   = (const float*)d_in[14];
    const float* bk   = (const float*)d_in[15];
    const float* Wv   = (const float*)d_in[16];
    const float* bv   = (const float*)d_in[17];
    const float* wval = (const float*)d_in[18];
    const float* bval = (const float*)d_in[19];
    const float* dm   = (const float*)d_in[20];
    float* out = (float*)d_out;
    int dup = (out_size >= 2 * Bb * Pp) ? 1 : 0;

    cudaFuncSetAttribute(k_fused, cudaFuncAttributeMaxDynamicSharedMemorySize, SMEM_FUSED);

    k_init<<<1, 32>>>();
    k_prep<<<(Pp * Ff / 4 + 255) / 256, 256>>>(pw);
    k_delta_stats<<<Bb, 256>>>(lat, lon, ut);
    k_ti<<<1, 256>>>(ut);
    k_qkv<<<dim3(Bb, 2, 3), 128>>>(user, poi, tod, dow, uw, pw, tw, dww,
                                   Wq, bq, Wk, bk, Wv, bv);
    k_attn2<<<Bb, 128>>>(lat, lon, ut);
    k_dm_stats<<<Rr, 256>>>(poi, dm);           // right before k_fused: dm rows L2-hot
    k_fused<<<dim3(79, Bb / 4), 256, SMEM_FUSED>>>(poi, dm, wval, bval, out, dup);
}

// round 10
// speedup vs baseline: 1.4559x; 1.0424x over previous
#include <cuda_runtime.h>
#include <cuda_bf16.h>
#include <mma.h>
#include <math_constants.h>

using namespace nvcuda;

// Problem dims
#define Bb   64
#define Ll   25
#define Ff   128
#define Pp   10000
#define Rr   (Bb*Ll)        // 1600 rows

// mega-kernel block ranges
#define NB_DM     1600
#define NB_DELTA  64
#define NB_TI     1
#define NB_QKV    (Bb*3)    // 192
#define NB_MEGA   (NB_DM + NB_DELTA + NB_TI + NB_QKV)

// ---------------- device scratch ----------------
// stats layout (int bits of nonnegative floats):
// 0 ds_max, 1 ds_min, 2 dt_max, 3 dt_min, 4 is_max, 5 is_min, 6 ti_max, 7 ti_min
__device__ int   g_stats[8];
__device__ float g_ti[Rr];
__device__ float g_q[Rr * Ff];
__device__ float g_k[Rr * Ff];
__device__ float g_v[Rr * Ff];
__device__ __nv_bfloat16 g_saoH[Rr * Ff];
__device__ __nv_bfloat16 g_saoR[Rr * Ff];
__device__ __nv_bfloat16 g_pwH[Pp * Ff];   // 2.56 MB
__device__ __nv_bfloat16 g_pwR[Pp * Ff];   // 2.56 MB

// ---------------- helpers ----------------
__device__ __forceinline__ float hav(float lat1, float lon1, float lat2, float lon2) {
    const float pc = 0.017453292519943295f;  // pi/180
    float a = 0.5f - cosf((lat2 - lat1) * pc) * 0.5f
            + cosf(lat1 * pc) * cosf(lat2 * pc) * (1.0f - cosf((lon2 - lon1) * pc)) * 0.5f;
    a = fminf(fmaxf(a, 0.0f), 1.0f);
    return 12742.0f * asinf(sqrtf(a));
}

__device__ __forceinline__ void blockMinMaxAtomic(float vmax, float vmin, int idxMax, int idxMin) {
    #pragma unroll
    for (int off = 16; off; off >>= 1) {
        vmax = fmaxf(vmax, __shfl_xor_sync(0xffffffffu, vmax, off));
        vmin = fminf(vmin, __shfl_xor_sync(0xffffffffu, vmin, off));
    }
    __shared__ float smax[8], smin[8];
    int warp = threadIdx.x >> 5, lane = threadIdx.x & 31;
    int nw = (blockDim.x + 31) >> 5;
    if (lane == 0) { smax[warp] = vmax; smin[warp] = vmin; }
    __syncthreads();
    if (warp == 0) {
        vmax = (lane < nw) ? smax[lane] : -CUDART_INF_F;
        vmin = (lane < nw) ? smin[lane] :  CUDART_INF_F;
        #pragma unroll
        for (int off = 4; off; off >>= 1) {
            vmax = fmaxf(vmax, __shfl_xor_sync(0xffffffffu, vmax, off));
            vmin = fminf(vmin, __shfl_xor_sync(0xffffffffu, vmin, off));
        }
        if (lane == 0) {
            atomicMax(&g_stats[idxMax], __float_as_int(vmax));
            atomicMin(&g_stats[idxMin], __float_as_int(vmin));
        }
    }
    __syncthreads();
}

// ---------------- launch 1: split pw into bf16 hi/res + init stats ----------------
__global__ void __launch_bounds__(256) k_prep(const float* __restrict__ pw) {
    if (blockIdx.x == 0 && threadIdx.x < 8)
        g_stats[threadIdx.x] = (threadIdx.x & 1) ? 0x7f800000 : 0;
    int i = blockIdx.x * 256 + threadIdx.x;           // one float4 per thread
    if (i < Pp * Ff / 4) {
        float4 v = ((const float4*)pw)[i];
        float xs[4] = {v.x, v.y, v.z, v.w};
        #pragma unroll
        for (int k = 0; k < 4; k++) {
            __nv_bfloat16 h = __float2bfloat16(xs[k]);
            g_pwH[i * 4 + k] = h;
            g_pwR[i * 4 + k] = __float2bfloat16(xs[k] - __bfloat162float(h));
        }
    }
}

// ---------------- launch 2: mega-kernel (dm stats | delta stats | ti | qkv) ----------------
// All four roles are mutually independent; running them in one grid overlaps the
// DRAM-streaming dm pass with the latency/FMA-bound qkv blocks.
__global__ void __launch_bounds__(256) k_mega(
    const int* __restrict__ poi, const float* __restrict__ dm,
    const float* __restrict__ lat, const float* __restrict__ lon, const float* __restrict__ ut,
    const int* __restrict__ user, const int* __restrict__ tod, const int* __restrict__ dow,
    const float* __restrict__ uw, const float* __restrict__ pw,
    const float* __restrict__ tw, const float* __restrict__ dww,
    const float* __restrict__ Wq, const float* __restrict__ bq,
    const float* __restrict__ Wk, const float* __restrict__ bk,
    const float* __restrict__ Wv, const float* __restrict__ bv) {
    int bid = blockIdx.x, tid = threadIdx.x;

    if (bid < NB_DM) {
        // -------- dm row min/max (also warms L2 for the fused epilogue) --------
        long row = poi[bid];
        const float4* r = (const float4*)(dm + row * (long)Pp);
        float vmax = -CUDART_INF_F, vmin = CUDART_INF_F;
        for (int c = tid; c < Pp / 4; c += 256) {
            float4 v = __ldg(&r[c]);
            vmax = fmaxf(vmax, fmaxf(fmaxf(v.x, v.y), fmaxf(v.z, v.w)));
            vmin = fminf(vmin, fminf(fminf(v.x, v.y), fminf(v.z, v.w)));
        }
        blockMinMaxAtomic(vmax, vmin, 4, 5);
        return;
    }
    if (bid < NB_DM + NB_DELTA) {
        // -------- per-batch delta_s / delta_t min/max --------
        int b = bid - NB_DM;
        const float* la = lat + b * Ll;
        const float* lo = lon + b * Ll;
        const float* u  = ut  + b * Ll;
        float dsmax = -CUDART_INF_F, dsmin = CUDART_INF_F;
        float dtmax = -CUDART_INF_F, dtmin = CUDART_INF_F;
        for (int idx = tid; idx < Ll * Ll; idx += 256) {
            int i = idx / Ll, j = idx % Ll;
            float ds = hav(la[i], lo[i], la[j], lo[j]);
            float dt = fabsf(u[i] - u[j]);
            dsmax = fmaxf(dsmax, ds); dsmin = fminf(dsmin, ds);
            dtmax = fmaxf(dtmax, dt); dtmin = fminf(dtmin, dt);
        }
        blockMinMaxAtomic(dsmax, dsmin, 0, 1);
        blockMinMaxAtomic(dtmax, dtmin, 2, 3);
        return;
    }
    if (bid < NB_DM + NB_DELTA + NB_TI) {
        // -------- time_interval + its min/max --------
        float vmax = -CUDART_INF_F, vmin = CUDART_INF_F;
        for (int i = tid; i < Rr; i += 256) {
            int l = i % Ll;
            float t = (l == 0) ? 0.0f : fabsf(ut[i] - ut[i - 1]);
            g_ti[i] = t;
            vmax = fmaxf(vmax, t); vmin = fminf(vmin, t);
        }
        blockMinMaxAtomic(vmax, vmin, 6, 7);
        return;
    }

    // -------- qkv: block = (b, z), halves of L via tid>>7; 13 accs/thread --------
    {
        int qi = bid - (NB_DM + NB_DELTA + NB_TI);
        int b = qi / 3, z = qi % 3;
        int half = tid >> 7, f = tid & 127;
        int l0 = half * 13;
        int nl = half ? 12 : 13;
        __shared__ float inp_s[2][13][Ff];

        for (int i = f; i < 13 * Ff; i += 128) {
            int l = i >> 7, ff = i & 127;
            float v = 0.0f;
            if (l < nl) {
                int base = b * Ll + l0 + l;
                v = uw[user[base] * Ff + ff] + pw[poi[base] * Ff + ff]
                  + tw[tod[base] * Ff + ff]  + dww[dow[base] * Ff + ff];
            }
            inp_s[half][l][ff] = v;
        }
        __syncthreads();

        const float* W    = (z == 0) ? Wq : (z == 1) ? Wk : Wv;
        const float* bias = (z == 0) ? bq : (z == 1) ? bk : bv;
        float*       dst  = (z == 0) ? g_q : (z == 1) ? g_k : g_v;

        float a[13];
        #pragma unroll
        for (int l = 0; l < 13; l++) a[l] = 0.f;
        #pragma unroll 4
        for (int g = 0; g < Ff; g++) {
            float w = W[g * Ff + f];
            #pragma unroll
            for (int l = 0; l < 13; l++) a[l] = fmaf(inp_s[half][l][g], w, a[l]);
        }
        float bf = bias[f];
        #pragma unroll
        for (int l = 0; l < 13; l++)
            if (l < nl) dst[(b * Ll + l0 + l) * Ff + f] = a[l] + bf;
    }
}

// ---------------- launch 3: scores + delta + softmax + attn@v ----------------
__global__ void __launch_bounds__(128) k_attn2(
    const float* __restrict__ lat, const float* __restrict__ lon, const float* __restrict__ ut) {
    __shared__ float q_s[Ll][132];
    __shared__ float k_s[Ll][132];
    __shared__ float sc[Ll][26];
    int b = blockIdx.x, tid = threadIdx.x;

    for (int i = tid; i < Ll * Ff; i += 128) {
        int l = i >> 7, f = i & 127;
        q_s[l][f] = g_q[(b * Ll + l) * Ff + f];
        k_s[l][f] = g_k[(b * Ll + l) * Ff + f];
    }
    int f = tid;
    float av[Ll];
    #pragma unroll
    for (int l = 0; l < Ll; l++) av[l] = g_v[(b * Ll + l) * Ff + f];
    __syncthreads();

    float invDs = 1.0f / (__int_as_float(g_stats[0]) - __int_as_float(g_stats[1]));
    float invDt = 1.0f / (__int_as_float(g_stats[2]) - __int_as_float(g_stats[3]));
    for (int idx = tid; idx < Ll * Ll; idx += 128) {
        int i = idx / Ll, j = idx % Ll;
        float s0 = 0.f, s1 = 0.f, s2 = 0.f, s3 = 0.f;
        #pragma unroll 8
        for (int f2 = 0; f2 < Ff; f2 += 4) {
            s0 = fmaf(q_s[i][f2 + 0], k_s[j][f2 + 0], s0);
            s1 = fmaf(q_s[i][f2 + 1], k_s[j][f2 + 1], s1);
            s2 = fmaf(q_s[i][f2 + 2], k_s[j][f2 + 2], s2);
            s3 = fmaf(q_s[i][f2 + 3], k_s[j][f2 + 3], s3);
        }
        float s = (s0 + s1) + (s2 + s3);
        int bi = b * Ll + i, bj = b * Ll + j;
        float ds = hav(lat[bi], lon[bi], lat[bj], lon[bj]);
        float dt = fabsf(ut[bi] - ut[bj]);
        sc[i][j] = s + 0.5f * (__expf(-ds * invDs) + __expf(-dt * invDt));
    }
    __syncthreads();

    if (tid < Ll) {
        float m = -CUDART_INF_F;
        for (int j = 0; j < Ll; j++) m = fmaxf(m, sc[tid][j]);
        float sum = 0.f;
        for (int j = 0; j < Ll; j++) sum += __expf(sc[tid][j] - m);
        float inv = 1.0f / sum;
        for (int j = 0; j < Ll; j++) sc[tid][j] = __expf(sc[tid][j] - m) * inv;
    }
    __syncthreads();

    for (int i = 0; i < Ll; i++) {
        float acc = 0.f;
        #pragma unroll
        for (int j = 0; j < Ll; j++) acc = fmaf(sc[i][j], av[j], acc);
        int idx = (b * Ll + i) * Ff + f;
        __nv_bfloat16 h = __float2bfloat16(acc);
        g_saoH[idx] = h;
        g_saoR[idx] = __float2bfloat16(acc - __bfloat162float(h));
    }
}

// ---------------- launch 4: fused GEMM (split-bf16 3-pass) + epilogue ----------------
// S(64x128) = sao(2 batches, padded 25->32 rows) @ pw^T tile;
// out[b,p] = bval + sum_l 0.5*w[l]*S[l,p]*(exp(-dm[poi,p]/S1)+exp(-ti/T1))
// dyn smem: AsH/AsR 64x136 + BsH/BsR 128x136 bf16 = 104448 B -> 2 blocks/SM.
// S(fp32 64x128 = 32KB) overlays the A region (34KB).
#define SMEM_FUSED 104448

__global__ void __launch_bounds__(128) k_fused(
    const int* __restrict__ poi,
    const float* __restrict__ dm, const float* __restrict__ wval,
    const float* __restrict__ bval, float* __restrict__ out, int dup) {
    extern __shared__ char smraw[];
    __nv_bfloat16* AsH = (__nv_bfloat16*)smraw;
    __nv_bfloat16* AsR = AsH + 64 * 136;
    __nv_bfloat16* BsH = AsR + 64 * 136;
    __nv_bfloat16* BsR = BsH + 128 * 136;
    float* S = (float*)smraw;               // overlays AsH/AsR after MMA
    __shared__ int   prow[2][Ll];
    __shared__ float cw[Ll], e2[2][Ll];

    int tid = threadIdx.x;
    int colTile = blockIdx.x * 128;
    int b0 = blockIdx.y * 2;

    if (tid < 2 * Ll) {
        int bt = tid / Ll, l = tid % Ll;
        int b = b0 + bt;
        prow[bt][l] = poi[b * Ll + l];
        float T1 = __int_as_float(g_stats[6]) - __int_as_float(g_stats[7]);
        e2[bt][l] = __expf(-g_ti[b * Ll + l] / T1);
        if (bt == 0) cw[l] = 0.5f * wval[l];
    }

    // stage A: 64 rows (2 batches x 32, rows 25..31 zero), uint4 = 8 bf16
    for (int i = tid; i < 64 * 16; i += 128) {
        int r = i >> 4, c8 = (i & 15) << 3;
        int bt = r >> 5, l = r & 31;
        uint4 vH = make_uint4(0, 0, 0, 0), vR = make_uint4(0, 0, 0, 0);
        if (l < Ll) {
            long off = ((long)(b0 + bt) * Ll + l) * Ff + c8;
            vH = *(const uint4*)(g_saoH + off);
            vR = *(const uint4*)(g_saoR + off);
        }
        *(uint4*)(AsH + r * 136 + c8) = vH;
        *(uint4*)(AsR + r * 136 + c8) = vR;
    }
    // stage B: 128 p-rows from pre-split pw (col_major frags -> no transpose)
    for (int i = tid; i < 128 * 16; i += 128) {
        int r = i >> 4, c8 = (i & 15) << 3;
        int p = colTile + r;
        uint4 vH = make_uint4(0, 0, 0, 0), vR = make_uint4(0, 0, 0, 0);
        if (p < Pp) {
            long off = (long)p * Ff + c8;
            vH = *(const uint4*)(g_pwH + off);
            vR = *(const uint4*)(g_pwR + off);
        }
        *(uint4*)(BsH + r * 136 + c8) = vH;
        *(uint4*)(BsR + r * 136 + c8) = vR;
    }
    __syncthreads();

    int w = tid >> 5, wm = w >> 1, wn = w & 1;   // 2x2 warps: each 32 rows x 64 cols
    wmma::fragment<wmma::accumulator, 16, 16, 16, float> acc[2][4];
    #pragma unroll
    for (int i = 0; i < 2; i++)
        #pragma unroll
        for (int j = 0; j < 4; j++) wmma::fill_fragment(acc[i][j], 0.0f);

    #pragma unroll
    for (int kk = 0; kk < Ff; kk += 16) {
        wmma::fragment<wmma::matrix_a, 16, 16, 16, __nv_bfloat16, wmma::row_major> aH[2], aR[2];
        wmma::fragment<wmma::matrix_b, 16, 16, 16, __nv_bfloat16, wmma::col_major> bH[4], bR[4];
        #pragma unroll
        for (int i = 0; i < 2; i++) {
            wmma::load_matrix_sync(aH[i], AsH + (wm * 32 + i * 16) * 136 + kk, 136);
            wmma::load_matrix_sync(aR[i], AsR + (wm * 32 + i * 16) * 136 + kk, 136);
        }
        #pragma unroll
        for (int j = 0; j < 4; j++) {
            wmma::load_matrix_sync(bH[j], BsH + (wn * 64 + j * 16) * 136 + kk, 136);
            wmma::load_matrix_sync(bR[j], BsR + (wn * 64 + j * 16) * 136 + kk, 136);
        }
        #pragma unroll
        for (int i = 0; i < 2; i++)
            #pragma unroll
            for (int j = 0; j < 4; j++) {
                wmma::mma_sync(acc[i][j], aH[i], bH[j], acc[i][j]);
                wmma::mma_sync(acc[i][j], aR[i], bH[j], acc[i][j]);
                wmma::mma_sync(acc[i][j], aH[i], bR[j], acc[i][j]);
            }
    }
    __syncthreads();   // all frag reads done before S overlays A region

    #pragma unroll
    for (int i = 0; i < 2; i++)
        #pragma unroll
        for (int j = 0; j < 4; j++)
            wmma::store_matrix_sync(S + (wm * 32 + i * 16) * 128 + wn * 64 + j * 16,
                                    acc[i][j], 128, wmma::mem_row_major);
    __syncthreads();

    // epilogue: thread = one p column, reduce over l for both batches
    int p = colTile + tid;
    if (p < Pp) {
        float invS1 = 1.0f / (__int_as_float(g_stats[4]) - __int_as_float(g_stats[5]));
        float bv0 = bval[0];
        #pragma unroll
        for (int bt = 0; bt < 2; bt++) {
            float a2 = bv0;
            #pragma unroll
            for (int l = 0; l < Ll; l++) {
                float m = S[(bt * 32 + l) * 128 + tid];
                float d = dm[(long)prow[bt][l] * Pp + p];
                a2 = fmaf(cw[l] * m, __expf(-d * invS1) + e2[bt][l], a2);
            }
            int b = b0 + bt;
            out[b * Pp + p] = a2;
            if (dup) out[Bb * Pp + b * Pp + p] = a2;
        }
    }
}

// ---------------- launch ----------------
extern "C" void kernel_launch(void* const* d_in, const int* in_sizes, int n_in,
                              void* d_out, int out_size) {
    const int*   user = (const int*)  d_in[0];
    const int*   poi  = (const int*)  d_in[1];
    // d_in[2] = cat (unused by reference)
    const float* lat  = (const float*)d_in[3];
    const float* lon  = (const float*)d_in[4];
    const int*   tod  = (const int*)  d_in[5];
    const int*   dow  = (const int*)  d_in[6];
    const float* ut   = (const float*)d_in[7];
    const float* uw   = (const float*)d_in[8];
    const float* pw   = (const float*)d_in[9];
    const float* tw   = (const float*)d_in[10];
    const float* dww  = (const float*)d_in[11];
    const float* Wq   = (const float*)d_in[12];
    const float* bq   = (const float*)d_in[13];
    const float* Wk   = (const float*)d_in[14];
    const float* bk   = (const float*)d_in[15];
    const float* Wv   = (const float*)d_in[16];
    const float* bv   = (const float*)d_in[17];
    const float* wval = (const float*)d_in[18];
    const float* bval = (const float*)d_in[19];
    const float* dm   = (const float*)d_in[20];
    float* out = (float*)d_out;
    int dup = (out_size >= 2 * Bb * Pp) ? 1 : 0;

    cudaFuncSetAttribute(k_fused, cudaFuncAttributeMaxDynamicSharedMemorySize, SMEM_FUSED);

    k_prep<<<(Pp * Ff / 4 + 255) / 256, 256>>>(pw);                       // launch 1
    k_mega<<<NB_MEGA, 256>>>(poi, dm, lat, lon, ut, user, tod, dow,       // launch 2
                             uw, pw, tw, dww, Wq, bq, Wk, bk, Wv, bv);
    k_attn2<<<Bb, 128>>>(lat, lon, ut);                                   // launch 3
    k_fused<<<dim3(79, Bb / 2), 128, SMEM_FUSED>>>(poi, dm, wval, bval,   // launch 4
                                                   out, dup);
}

// round 11
// speedup vs baseline: 1.6412x; 1.1273x over previous
#include <cuda_runtime.h>
#include <cuda_bf16.h>
#include <mma.h>
#include <math_constants.h>

using namespace nvcuda;

// Problem dims
#define Bb   64
#define Ll   25
#define Ff   128
#define Pp   10000
#define Rr   (Bb*Ll)        // 1600 rows

// mega-kernel block ranges
#define NB_DM     1600
#define NB_DELTA  64
#define NB_TI     1
#define NB_QKV    (Bb*3)    // 192
#define NB_MEGA   (NB_DM + NB_DELTA + NB_TI + NB_QKV)

// ---------------- device scratch ----------------
// stats layout (int bits of nonnegative floats):
// 0 ds_max, 1 ds_min, 2 dt_max, 3 dt_min, 4 is_max, 5 is_min, 6 ti_max, 7 ti_min
__device__ int   g_stats[8];
__device__ float g_ti[Rr];
__device__ float g_q[Rr * Ff];
__device__ float g_k[Rr * Ff];
__device__ float g_v[Rr * Ff];
__device__ __nv_bfloat16 g_saoH[Rr * Ff];
__device__ __nv_bfloat16 g_saoR[Rr * Ff];
__device__ __nv_bfloat16 g_pwH[Pp * Ff];   // 2.56 MB
__device__ __nv_bfloat16 g_pwR[Pp * Ff];   // 2.56 MB

// ---------------- helpers ----------------
__device__ __forceinline__ float hav(float lat1, float lon1, float lat2, float lon2) {
    const float pc = 0.017453292519943295f;  // pi/180
    float a = 0.5f - cosf((lat2 - lat1) * pc) * 0.5f
            + cosf(lat1 * pc) * cosf(lat2 * pc) * (1.0f - cosf((lon2 - lon1) * pc)) * 0.5f;
    a = fminf(fmaxf(a, 0.0f), 1.0f);
    return 12742.0f * asinf(sqrtf(a));
}

__device__ __forceinline__ void blockMinMaxAtomic(float vmax, float vmin, int idxMax, int idxMin) {
    #pragma unroll
    for (int off = 16; off; off >>= 1) {
        vmax = fmaxf(vmax, __shfl_xor_sync(0xffffffffu, vmax, off));
        vmin = fminf(vmin, __shfl_xor_sync(0xffffffffu, vmin, off));
    }
    __shared__ float smax[8], smin[8];
    int warp = threadIdx.x >> 5, lane = threadIdx.x & 31;
    int nw = (blockDim.x + 31) >> 5;
    if (lane == 0) { smax[warp] = vmax; smin[warp] = vmin; }
    __syncthreads();
    if (warp == 0) {
        vmax = (lane < nw) ? smax[lane] : -CUDART_INF_F;
        vmin = (lane < nw) ? smin[lane] :  CUDART_INF_F;
        #pragma unroll
        for (int off = 4; off; off >>= 1) {
            vmax = fmaxf(vmax, __shfl_xor_sync(0xffffffffu, vmax, off));
            vmin = fminf(vmin, __shfl_xor_sync(0xffffffffu, vmin, off));
        }
        if (lane == 0) {
            atomicMax(&g_stats[idxMax], __float_as_int(vmax));
            atomicMin(&g_stats[idxMin], __float_as_int(vmin));
        }
    }
    __syncthreads();
}

// ---------------- launch 1: split pw into bf16 hi/res + init stats ----------------
__global__ void __launch_bounds__(256) k_prep(const float* __restrict__ pw) {
    if (blockIdx.x == 0 && threadIdx.x < 8)
        g_stats[threadIdx.x] = (threadIdx.x & 1) ? 0x7f800000 : 0;
    int i = blockIdx.x * 256 + threadIdx.x;           // one float4 per thread
    if (i < Pp * Ff / 4) {
        float4 v = ((const float4*)pw)[i];
        float xs[4] = {v.x, v.y, v.z, v.w};
        #pragma unroll
        for (int k = 0; k < 4; k++) {
            __nv_bfloat16 h = __float2bfloat16(xs[k]);
            g_pwH[i * 4 + k] = h;
            g_pwR[i * 4 + k] = __float2bfloat16(xs[k] - __bfloat162float(h));
        }
    }
}

// ---------------- launch 2: mega-kernel (dm stats | delta stats | ti | qkv) ----------------
__global__ void __launch_bounds__(256) k_mega(
    const int* __restrict__ poi, const float* __restrict__ dm,
    const float* __restrict__ lat, const float* __restrict__ lon, const float* __restrict__ ut,
    const int* __restrict__ user, const int* __restrict__ tod, const int* __restrict__ dow,
    const float* __restrict__ uw, const float* __restrict__ pw,
    const float* __restrict__ tw, const float* __restrict__ dww,
    const float* __restrict__ Wq, const float* __restrict__ bq,
    const float* __restrict__ Wk, const float* __restrict__ bk,
    const float* __restrict__ Wv, const float* __restrict__ bv) {
    int bid = blockIdx.x, tid = threadIdx.x;

    if (bid < NB_DM) {
        long row = poi[bid];
        const float4* r = (const float4*)(dm + row * (long)Pp);
        float vmax = -CUDART_INF_F, vmin = CUDART_INF_F;
        for (int c = tid; c < Pp / 4; c += 256) {
            float4 v = __ldg(&r[c]);
            vmax = fmaxf(vmax, fmaxf(fmaxf(v.x, v.y), fmaxf(v.z, v.w)));
            vmin = fminf(vmin, fminf(fminf(v.x, v.y), fminf(v.z, v.w)));
        }
        blockMinMaxAtomic(vmax, vmin, 4, 5);
        return;
    }
    if (bid < NB_DM + NB_DELTA) {
        int b = bid - NB_DM;
        const float* la = lat + b * Ll;
        const float* lo = lon + b * Ll;
        const float* u  = ut  + b * Ll;
        float dsmax = -CUDART_INF_F, dsmin = CUDART_INF_F;
        float dtmax = -CUDART_INF_F, dtmin = CUDART_INF_F;
        for (int idx = tid; idx < Ll * Ll; idx += 256) {
            int i = idx / Ll, j = idx % Ll;
            float ds = hav(la[i], lo[i], la[j], lo[j]);
            float dt = fabsf(u[i] - u[j]);
            dsmax = fmaxf(dsmax, ds); dsmin = fminf(dsmin, ds);
            dtmax = fmaxf(dtmax, dt); dtmin = fminf(dtmin, dt);
        }
        blockMinMaxAtomic(dsmax, dsmin, 0, 1);
        blockMinMaxAtomic(dtmax, dtmin, 2, 3);
        return;
    }
    if (bid < NB_DM + NB_DELTA + NB_TI) {
        float vmax = -CUDART_INF_F, vmin = CUDART_INF_F;
        for (int i = tid; i < Rr; i += 256) {
            int l = i % Ll;
            float t = (l == 0) ? 0.0f : fabsf(ut[i] - ut[i - 1]);
            g_ti[i] = t;
            vmax = fmaxf(vmax, t); vmin = fminf(vmin, t);
        }
        blockMinMaxAtomic(vmax, vmin, 6, 7);
        return;
    }

    // -------- qkv: block = (b, z), halves of L via tid>>7; 13 accs/thread --------
    {
        int qi = bid - (NB_DM + NB_DELTA + NB_TI);
        int b = qi / 3, z = qi % 3;
        int half = tid >> 7, f = tid & 127;
        int l0 = half * 13;
        int nl = half ? 12 : 13;
        __shared__ float inp_s[2][13][Ff];

        for (int i = f; i < 13 * Ff; i += 128) {
            int l = i >> 7, ff = i & 127;
            float v = 0.0f;
            if (l < nl) {
                int base = b * Ll + l0 + l;
                v = uw[user[base] * Ff + ff] + pw[poi[base] * Ff + ff]
                  + tw[tod[base] * Ff + ff]  + dww[dow[base] * Ff + ff];
            }
            inp_s[half][l][ff] = v;
        }
        __syncthreads();

        const float* W    = (z == 0) ? Wq : (z == 1) ? Wk : Wv;
        const float* bias = (z == 0) ? bq : (z == 1) ? bk : bv;
        float*       dst  = (z == 0) ? g_q : (z == 1) ? g_k : g_v;

        float a[13];
        #pragma unroll
        for (int l = 0; l < 13; l++) a[l] = 0.f;
        #pragma unroll 4
        for (int g = 0; g < Ff; g++) {
            float w = W[g * Ff + f];
            #pragma unroll
            for (int l = 0; l < 13; l++) a[l] = fmaf(inp_s[half][l][g], w, a[l]);
        }
        float bf = bias[f];
        #pragma unroll
        for (int l = 0; l < 13; l++)
            if (l < nl) dst[(b * Ll + l0 + l) * Ff + f] = a[l] + bf;
    }
}

// ---------------- launch 3: scores + delta + softmax + attn@v ----------------
__global__ void __launch_bounds__(128) k_attn2(
    const float* __restrict__ lat, const float* __restrict__ lon, const float* __restrict__ ut) {
    __shared__ float q_s[Ll][132];
    __shared__ float k_s[Ll][132];
    __shared__ float sc[Ll][26];
    int b = blockIdx.x, tid = threadIdx.x;

    for (int i = tid; i < Ll * Ff; i += 128) {
        int l = i >> 7, f = i & 127;
        q_s[l][f] = g_q[(b * Ll + l) * Ff + f];
        k_s[l][f] = g_k[(b * Ll + l) * Ff + f];
    }
    int f = tid;
    float av[Ll];
    #pragma unroll
    for (int l = 0; l < Ll; l++) av[l] = g_v[(b * Ll + l) * Ff + f];
    __syncthreads();

    float invDs = 1.0f / (__int_as_float(g_stats[0]) - __int_as_float(g_stats[1]));
    float invDt = 1.0f / (__int_as_float(g_stats[2]) - __int_as_float(g_stats[3]));
    for (int idx = tid; idx < Ll * Ll; idx += 128) {
        int i = idx / Ll, j = idx % Ll;
        float s0 = 0.f, s1 = 0.f, s2 = 0.f, s3 = 0.f;
        #pragma unroll 8
        for (int f2 = 0; f2 < Ff; f2 += 4) {
            s0 = fmaf(q_s[i][f2 + 0], k_s[j][f2 + 0], s0);
            s1 = fmaf(q_s[i][f2 + 1], k_s[j][f2 + 1], s1);
            s2 = fmaf(q_s[i][f2 + 2], k_s[j][f2 + 2], s2);
            s3 = fmaf(q_s[i][f2 + 3], k_s[j][f2 + 3], s3);
        }
        float s = (s0 + s1) + (s2 + s3);
        int bi = b * Ll + i, bj = b * Ll + j;
        float ds = hav(lat[bi], lon[bi], lat[bj], lon[bj]);
        float dt = fabsf(ut[bi] - ut[bj]);
        sc[i][j] = s + 0.5f * (__expf(-ds * invDs) + __expf(-dt * invDt));
    }
    __syncthreads();

    if (tid < Ll) {
        float m = -CUDART_INF_F;
        for (int j = 0; j < Ll; j++) m = fmaxf(m, sc[tid][j]);
        float sum = 0.f;
        for (int j = 0; j < Ll; j++) sum += __expf(sc[tid][j] - m);
        float inv = 1.0f / sum;
        for (int j = 0; j < Ll; j++) sc[tid][j] = __expf(sc[tid][j] - m) * inv;
    }
    __syncthreads();

    for (int i = 0; i < Ll; i++) {
        float acc = 0.f;
        #pragma unroll
        for (int j = 0; j < Ll; j++) acc = fmaf(sc[i][j], av[j], acc);
        int idx = (b * Ll + i) * Ff + f;
        __nv_bfloat16 h = __float2bfloat16(acc);
        g_saoH[idx] = h;
        g_saoR[idx] = __float2bfloat16(acc - __bfloat162float(h));
    }
}

// ---------------- launch 4: fused GEMM (split-bf16 3-pass, restaged B) + epilogue ----------------
// S(64x128) = sao(2 batches, padded 25->32 rows) @ pw^T tile.
// Pass structure: stage BsH -> (aH*bH + aR*bH) over all k; restage same buffer
// with BsR -> (aH*bR) over all k. Accumulators persist in registers.
// smem: AsH/AsR 64x136 + Bs 128x136 bf16 = 69632 B; S(fp32 64x128=32KB) overlays A.
// 256 threads (8 warps, 2x4 grid, 32x32 per warp) -> 2x the warps of the old
// 128-thread version with 33% less smem.
#define SMEM_FUSED 69632

__global__ void __launch_bounds__(256) k_fused(
    const int* __restrict__ poi,
    const float* __restrict__ dm, const float* __restrict__ wval,
    const float* __restrict__ bval, float* __restrict__ out, int dup) {
    extern __shared__ char smraw[];
    __nv_bfloat16* AsH = (__nv_bfloat16*)smraw;
    __nv_bfloat16* AsR = AsH + 64 * 136;
    __nv_bfloat16* Bs  = AsR + 64 * 136;
    float* S = (float*)smraw;               // overlays AsH/AsR after MMA
    __shared__ int   prow[2][Ll];
    __shared__ float cw[Ll], e2[2][Ll];

    int tid = threadIdx.x;
    int colTile = blockIdx.x * 128;
    int b0 = blockIdx.y * 2;

    if (tid < 2 * Ll) {
        int bt = tid / Ll, l = tid % Ll;
        int b = b0 + bt;
        prow[bt][l] = poi[b * Ll + l];
        float T1 = __int_as_float(g_stats[6]) - __int_as_float(g_stats[7]);
        e2[bt][l] = __expf(-g_ti[b * Ll + l] / T1);
        if (bt == 0) cw[l] = 0.5f * wval[l];
    }

    // stage A (both H and R): 64 rows (2 batches x 32, rows 25..31 zero), uint4 = 8 bf16
    for (int i = tid; i < 64 * 16; i += 256) {
        int r = i >> 4, c8 = (i & 15) << 3;
        int bt = r >> 5, l = r & 31;
        uint4 vH = make_uint4(0, 0, 0, 0), vR = make_uint4(0, 0, 0, 0);
        if (l < Ll) {
            long off = ((long)(b0 + bt) * Ll + l) * Ff + c8;
            vH = *(const uint4*)(g_saoH + off);
            vR = *(const uint4*)(g_saoR + off);
        }
        *(uint4*)(AsH + r * 136 + c8) = vH;
        *(uint4*)(AsR + r * 136 + c8) = vR;
    }
    // stage B = pwH tile
    for (int i = tid; i < 128 * 16; i += 256) {
        int r = i >> 4, c8 = (i & 15) << 3;
        int p = colTile + r;
        uint4 vH = make_uint4(0, 0, 0, 0);
        if (p < Pp) vH = *(const uint4*)(g_pwH + (long)p * Ff + c8);
        *(uint4*)(Bs + r * 136 + c8) = vH;
    }
    __syncthreads();

    int w = tid >> 5, wm = w >> 2, wn = w & 3;   // 2x4 warps: each 32 rows x 32 cols
    wmma::fragment<wmma::accumulator, 16, 16, 16, float> acc[2][2];
    #pragma unroll
    for (int i = 0; i < 2; i++)
        #pragma unroll
        for (int j = 0; j < 2; j++) wmma::fill_fragment(acc[i][j], 0.0f);

    // pass 1+2: aH*bH + aR*bH
    #pragma unroll
    for (int kk = 0; kk < Ff; kk += 16) {
        wmma::fragment<wmma::matrix_a, 16, 16, 16, __nv_bfloat16, wmma::row_major> aH[2], aR[2];
        wmma::fragment<wmma::matrix_b, 16, 16, 16, __nv_bfloat16, wmma::col_major> bH[2];
        #pragma unroll
        for (int i = 0; i < 2; i++) {
            wmma::load_matrix_sync(aH[i], AsH + (wm * 32 + i * 16) * 136 + kk, 136);
            wmma::load_matrix_sync(aR[i], AsR + (wm * 32 + i * 16) * 136 + kk, 136);
        }
        #pragma unroll
        for (int j = 0; j < 2; j++)
            wmma::load_matrix_sync(bH[j], Bs + (wn * 32 + j * 16) * 136 + kk, 136);
        #pragma unroll
        for (int i = 0; i < 2; i++)
            #pragma unroll
            for (int j = 0; j < 2; j++) {
                wmma::mma_sync(acc[i][j], aH[i], bH[j], acc[i][j]);
                wmma::mma_sync(acc[i][j], aR[i], bH[j], acc[i][j]);
            }
    }
    __syncthreads();

    // restage B = pwR tile (same buffer)
    for (int i = tid; i < 128 * 16; i += 256) {
        int r = i >> 4, c8 = (i & 15) << 3;
        int p = colTile + r;
        uint4 vR = make_uint4(0, 0, 0, 0);
        if (p < Pp) vR = *(const uint4*)(g_pwR + (long)p * Ff + c8);
        *(uint4*)(Bs + r * 136 + c8) = vR;
    }
    __syncthreads();

    // pass 3: aH*bR
    #pragma unroll
    for (int kk = 0; kk < Ff; kk += 16) {
        wmma::fragment<wmma::matrix_a, 16, 16, 16, __nv_bfloat16, wmma::row_major> aH[2];
        wmma::fragment<wmma::matrix_b, 16, 16, 16, __nv_bfloat16, wmma::col_major> bR[2];
        #pragma unroll
        for (int i = 0; i < 2; i++)
            wmma::load_matrix_sync(aH[i], AsH + (wm * 32 + i * 16) * 136 + kk, 136);
        #pragma unroll
        for (int j = 0; j < 2; j++)
            wmma::load_matrix_sync(bR[j], Bs + (wn * 32 + j * 16) * 136 + kk, 136);
        #pragma unroll
        for (int i = 0; i < 2; i++)
            #pragma unroll
            for (int j = 0; j < 2; j++)
                wmma::mma_sync(acc[i][j], aH[i], bR[j], acc[i][j]);
    }
    __syncthreads();   // all frag reads done before S overlays A region

    #pragma unroll
    for (int i = 0; i < 2; i++)
        #pragma unroll
        for (int j = 0; j < 2; j++)
            wmma::store_matrix_sync(S + (wm * 32 + i * 16) * 128 + wn * 32 + j * 16,
                                    acc[i][j], 128, wmma::mem_row_major);
    __syncthreads();

    // epilogue: 256 threads -> thread = (p column, batch); 25 independent dm loads each
    int col = tid & 127, bt = tid >> 7;
    int p = colTile + col;
    if (p < Pp) {
        float invS1 = 1.0f / (__int_as_float(g_stats[4]) - __int_as_float(g_stats[5]));
        float a2 = bval[0];
        #pragma unroll
        for (int l = 0; l < Ll; l++) {
            float m = S[(bt * 32 + l) * 128 + col];
            float d = dm[(long)prow[bt][l] * Pp + p];
            a2 = fmaf(cw[l] * m, __expf(-d * invS1) + e2[bt][l], a2);
        }
        int b = b0 + bt;
        out[b * Pp + p] = a2;
        if (dup) out[Bb * Pp + b * Pp + p] = a2;
    }
}

// ---------------- launch ----------------
extern "C" void kernel_launch(void* const* d_in, const int* in_sizes, int n_in,
                              void* d_out, int out_size) {
    const int*   user = (const int*)  d_in[0];
    const int*   poi  = (const int*)  d_in[1];
    // d_in[2] = cat (unused by reference)
    const float* lat  = (const float*)d_in[3];
    const float* lon  = (const float*)d_in[4];
    const int*   tod  = (const int*)  d_in[5];
    const int*   dow  = (const int*)  d_in[6];
    const float* ut   = (const float*)d_in[7];
    const float* uw   = (const float*)d_in[8];
    const float* pw   = (const float*)d_in[9];
    const float* tw   = (const float*)d_in[10];
    const float* dww  = (const float*)d_in[11];
    const float* Wq   = (const float*)d_in[12];
    const float* bq   = (const float*)d_in[13];
    const float* Wk   = (const float*)d_in[14];
    const float* bk   = (const float*)d_in[15];
    const float* Wv   = (const float*)d_in[16];
    const float* bv   = (const float*)d_in[17];
    const float* wval = (const float*)d_in[18];
    const float* bval = (const float*)d_in[19];
    const float* dm   = (const float*)d_in[20];
    float* out = (float*)d_out;
    int dup = (out_size >= 2 * Bb * Pp) ? 1 : 0;

    cudaFuncSetAttribute(k_fused, cudaFuncAttributeMaxDynamicSharedMemorySize, SMEM_FUSED);

    k_prep<<<(Pp * Ff / 4 + 255) / 256, 256>>>(pw);                       // launch 1
    k_mega<<<NB_MEGA, 256>>>(poi, dm, lat, lon, ut, user, tod, dow,       // launch 2
                             uw, pw, tw, dww, Wq, bq, Wk, bk, Wv, bv);
    k_attn2<<<Bb, 128>>>(lat, lon, ut);                                   // launch 3
    k_fused<<<dim3(79, Bb / 2), 256, SMEM_FUSED>>>(poi, dm, wval, bval,   // launch 4
                                                   out, dup);
}